// round 12
// baseline (speedup 1.0000x reference)
#include <cuda_runtime.h>
#include <cstdint>

// out[b,f,m] = floor(log2( sum_h (x+1)^2 * fb[m,h] )), h<257
// mma.sync m16n8k8 TF32 3-pass emulation over k=0..255 (8 chunks of 32),
// k=256 handled as exact fp32 rank-1 update in the epilogue.
// Persistent CTAs (296 = exactly 1 wave) + atomic tile ticket (512 tiles).
// Ticket reset folded into prep_kernel: 2 launches total.

#define KREAL   257
#define NMELS   64
#define XSTR    512
#define MTILE   128
#define TPB     512
#define NCHUNK  8
#define NTILES  512
#define GRID    296

#define AROWB   144                         // padded row: 36 floats
#define A_BYTES (MTILE * AROWB)             // 18432 per buffer
#define B_F4    1024                        // [t(4)][nt(8)][lane(32)] float4
#define B_BYTES (B_F4 * 16)                 // 16384 per buffer
#define EDGE_OFF (2 * A_BYTES + 2 * B_BYTES)       // 69632
#define SMEM_BYTES (EDGE_OFF + (MTILE + NMELS) * 4) // 70400

__device__ float4 g_fbFrag[NCHUNK * B_F4];
__device__ unsigned g_ticket;

__device__ __forceinline__ float tf32_hi(float v) {
    unsigned h;
    asm("cvt.rna.tf32.f32 %0, %1;" : "=r"(h) : "f"(v));
    return __uint_as_float(h);
}
__device__ __forceinline__ unsigned smem_u32(const void* p) {
    unsigned a;
    asm("{ .reg .u64 t; cvta.to.shared.u64 t, %1; cvt.u32.u64 %0, t; }" : "=r"(a) : "l"(p));
    return a;
}
#define CP_ASYNC16(dst, src) \
    asm volatile("cp.async.ca.shared.global [%0], [%1], 16;" :: "r"(dst), "l"(src))
#define CP_COMMIT() asm volatile("cp.async.commit_group;" ::: "memory")
#define CP_WAIT0()  asm volatile("cp.async.wait_group 0;" ::: "memory")

__device__ __forceinline__ void mma8(float* d,
                                     float a0, float a1, float a2, float a3,
                                     float b0, float b1) {
    asm volatile(
        "mma.sync.aligned.m16n8k8.row.col.f32.tf32.tf32.f32 "
        "{%0,%1,%2,%3}, {%4,%5,%6,%7}, {%8,%9}, {%0,%1,%2,%3};"
        : "+f"(d[0]), "+f"(d[1]), "+f"(d[2]), "+f"(d[3])
        : "r"(__float_as_uint(a0)), "r"(__float_as_uint(a1)),
          "r"(__float_as_uint(a2)), "r"(__float_as_uint(a3)),
          "r"(__float_as_uint(b0)), "r"(__float_as_uint(b1)));
}

// ---- prep: fb -> fragment-ordered float4 (b0hi,b0lo,b1hi,b1lo), k<256 ----
// Also resets the persistent-kernel tile ticket (block 0).
__global__ void prep_kernel(const float* __restrict__ fb) {
    if (blockIdx.x == 0 && threadIdx.x == 0) g_ticket = GRID;
    int ch = blockIdx.x;
    for (int i = threadIdx.x; i < B_F4; i += blockDim.x) {
        int lane = i & 31;
        int nt   = (i >> 5) & 7;
        int t    = (i >> 8) & 3;
        int n  = nt * 8 + (lane >> 2);
        int k0 = ch * 32 + t * 8 + (lane & 3);
        float v0 = fb[n * KREAL + k0];
        float v1 = fb[n * KREAL + k0 + 4];
        float h0 = tf32_hi(v0), h1 = tf32_hi(v1);
        g_fbFrag[ch * B_F4 + i] = make_float4(h0, v0 - h0, h1, v1 - h1);
    }
}

__global__ void __launch_bounds__(TPB, 2)
lmfe_kernel(const float* __restrict__ x, const float* __restrict__ fb,
            float* __restrict__ out) {
    extern __shared__ char smemRaw[];
    float4* sB    = reinterpret_cast<float4*>(smemRaw + 2 * A_BYTES);
    float*  sMag  = reinterpret_cast<float*>(smemRaw + EDGE_OFF);       // [128]
    float*  sFbc  = sMag + MTILE;                                       // [64]
    __shared__ unsigned sTile;
    const unsigned sAaddr = smem_u32(smemRaw);
    const unsigned sBaddr = smem_u32(sB);

    const int tid  = threadIdx.x;
    const int wid  = tid >> 5;
    const int lane = tid & 31;

    // fb[:,256] once (never overwritten)
    if (tid < NMELS) sFbc[tid] = fb[tid * KREAL + 256];

    // staging maps
    const int aRow = tid >> 2;
    const int aQ   = tid & 3;
    const unsigned aDstBase = sAaddr + aRow * AROWB + aQ * 32;
    const float4* bSrcBase = g_fbFrag + tid;

    // warp tile map
    const int mGrp  = wid & 7;
    const int nHalf = wid >> 3;
    const int g   = lane >> 2;
    const int tig = lane & 3;
    const float* aF = reinterpret_cast<const float*>(smemRaw) + (mGrp * 16 + g) * 36 + tig;
    const int row0L = mGrp * 16 + g;
    const int col0  = nHalf * 32 + 2 * tig;

    unsigned tile = blockIdx.x;

#pragma unroll 1
    while (tile < NTILES) {
        const size_t rowBase = (size_t)tile * MTILE;
        const float* xp = x + (rowBase + (size_t)aRow) * XSTR + aQ * 8;

        // ---- stage chunk 0 + mag256 column ----
        CP_ASYNC16(aDstBase,      (const void*)xp);
        CP_ASYNC16(aDstBase + 16, (const void*)(xp + 4));
        CP_ASYNC16(sBaddr + tid * 16,         (const void*)bSrcBase);
        CP_ASYNC16(sBaddr + (tid + TPB) * 16, (const void*)(bSrcBase + TPB));
        CP_COMMIT();
        if (tid < MTILE) {
            float v = x[(rowBase + (size_t)tid) * XSTR + 256] + 1.0f;
            sMag[tid] = v * v;
        }
        CP_WAIT0();
        __syncthreads();

        float acc[4][4];
#pragma unroll
        for (int nt = 0; nt < 4; ++nt)
#pragma unroll
            for (int r = 0; r < 4; ++r) acc[nt][r] = 0.0f;

#pragma unroll 1
        for (int ch = 0; ch < NCHUNK; ++ch) {
            if (ch + 1 < NCHUNK) {
                const int nb = (ch + 1) & 1;
                const float* aS = xp + (ch + 1) * 32;
                CP_ASYNC16(aDstBase + nb * A_BYTES,      (const void*)aS);
                CP_ASYNC16(aDstBase + nb * A_BYTES + 16, (const void*)(aS + 4));
                const unsigned bD = sBaddr + nb * B_BYTES;
                const float4* bS = bSrcBase + (ch + 1) * B_F4;
                CP_ASYNC16(bD + tid * 16,         (const void*)bS);
                CP_ASYNC16(bD + (tid + TPB) * 16, (const void*)(bS + TPB));
                CP_COMMIT();
            }

            const int b = ch & 1;
            const float*  aT   = aF + b * (A_BYTES / 4);
            const float4* bBuf = sB + b * B_F4 + nHalf * 128 + lane;

#pragma unroll
            for (int t = 0; t < 4; ++t) {
                float4 b0 = bBuf[t * 256];
                float4 b1 = bBuf[t * 256 + 32];
                float4 b2 = bBuf[t * 256 + 64];
                float4 b3 = bBuf[t * 256 + 96];
                const float* aP = aT + t * 8;
                float r0 = aP[0], r1 = aP[288], r2 = aP[4], r3 = aP[292];
                float m0 = (r0 + 1.0f) * (r0 + 1.0f);
                float m1 = (r1 + 1.0f) * (r1 + 1.0f);
                float m2 = (r2 + 1.0f) * (r2 + 1.0f);
                float m3 = (r3 + 1.0f) * (r3 + 1.0f);
                float h0 = tf32_hi(m0), h1 = tf32_hi(m1);
                float h2 = tf32_hi(m2), h3 = tf32_hi(m3);
                float l0 = m0 - h0, l1 = m1 - h1, l2 = m2 - h2, l3 = m3 - h3;

                mma8(acc[0], h0, h1, h2, h3, b0.x, b0.z);
                mma8(acc[1], h0, h1, h2, h3, b1.x, b1.z);
                mma8(acc[2], h0, h1, h2, h3, b2.x, b2.z);
                mma8(acc[3], h0, h1, h2, h3, b3.x, b3.z);
                mma8(acc[0], h0, h1, h2, h3, b0.y, b0.w);
                mma8(acc[1], h0, h1, h2, h3, b1.y, b1.w);
                mma8(acc[2], h0, h1, h2, h3, b2.y, b2.w);
                mma8(acc[3], h0, h1, h2, h3, b3.y, b3.w);
                mma8(acc[0], l0, l1, l2, l3, b0.x, b0.z);
                mma8(acc[1], l0, l1, l2, l3, b1.x, b1.z);
                mma8(acc[2], l0, l1, l2, l3, b2.x, b2.z);
                mma8(acc[3], l0, l1, l2, l3, b3.x, b3.z);
            }

            if (ch + 1 < NCHUNK) CP_WAIT0();
            __syncthreads();
        }

        // ---- epilogue: add exact k=256 term, then exponent extract ----
        const float a0m = sMag[row0L];
        const float a1m = sMag[row0L + 8];
        const size_t r0w = rowBase + (size_t)row0L;
#pragma unroll
        for (int nt = 0; nt < 4; ++nt) {
            float2 fc = *reinterpret_cast<const float2*>(sFbc + col0 + nt * 8);
            float v00 = fmaf(a0m, fc.x, acc[nt][0]);
            float v01 = fmaf(a0m, fc.y, acc[nt][1]);
            float v10 = fmaf(a1m, fc.x, acc[nt][2]);
            float v11 = fmaf(a1m, fc.y, acc[nt][3]);
            float2 o0, o1;
            o0.x = (float)(int)(((__float_as_uint(v00) >> 23) & 0xFF) - 127);
            o0.y = (float)(int)(((__float_as_uint(v01) >> 23) & 0xFF) - 127);
            o1.x = (float)(int)(((__float_as_uint(v10) >> 23) & 0xFF) - 127);
            o1.y = (float)(int)(((__float_as_uint(v11) >> 23) & 0xFF) - 127);
            *reinterpret_cast<float2*>(out + r0w * NMELS + col0 + nt * 8)       = o0;
            *reinterpret_cast<float2*>(out + (r0w + 8) * NMELS + col0 + nt * 8) = o1;
        }

        // ---- next tile via ticket ----
        __syncthreads();
        if (tid == 0) sTile = atomicAdd(&g_ticket, 1u);
        __syncthreads();
        tile = sTile;
    }
}

extern "C" void kernel_launch(void* const* d_in, const int* in_sizes, int n_in,
                              void* d_out, int out_size) {
    const float* x  = (const float*)d_in[0];   // (256,256,512,1) fp32
    const float* fb = (const float*)d_in[1];   // (64,257) fp32
    float* out = (float*)d_out;                // (256,256,64,1) fp32

    prep_kernel<<<NCHUNK, 256>>>(fb);          // also resets the tile ticket

    cudaFuncSetAttribute(lmfe_kernel,
                         cudaFuncAttributeMaxDynamicSharedMemorySize, SMEM_BYTES);
    lmfe_kernel<<<GRID, TPB, SMEM_BYTES>>>(x, fb, out);
}